// round 2
// baseline (speedup 1.0000x reference)
#include <cuda_runtime.h>
#include <math.h>

// ---------------------------------------------------------------------------
// RainbowNet fused inference.
// Key algebraic reduction: only out[:,0,:] (cls row) of attention is used and
// the cls query is batch-independent, so attention reduces to:
//   scores[h,j] = x_j . wscore_h + c_h          (wscore precomputed)
//   pooled      = sum_h (sum_j a_hj x_j) @ M_h + c_pool   (M_h precomputed)
// ---------------------------------------------------------------------------

constexpr int BQ       = 8192;
constexpr int STATE_SZ = 1360;
constexpr int TRUNK_IN = 1488;   // 1360 + 128
constexpr int TRUNK_H  = 1024;
constexpr int HALF_H   = 512;
constexpr int ATOMS    = 51;
constexpr int ACTIONS  = 81;
constexpr int ADV_N    = ACTIONS * ATOMS;  // 4131

// scratch offsets (floats)
constexpr size_t OFF_XW   = 0;                      // 8192*512
constexpr size_t OFF_POOL = 4194304;                // 8192*128
constexpr size_t OFF_Z0   = 5242880;                // 8192*1024
constexpr size_t OFF_H1   = 13631488;               // 8192*1024
constexpr size_t OFF_VALH = 22020096;               // 8192*512
constexpr size_t OFF_ADVH = 26214400;               // 8192*512
constexpr size_t OFF_VAL  = 30408704;               // 8192*51
constexpr size_t OFF_ADV  = 30826496;               // 8192*4131
constexpr size_t OFF_QVEC = 64667648;               // 128
constexpr size_t OFF_WS   = 64667776;               // 512
constexpr size_t OFF_CS   = 64668288;               // 64 (4 used)
constexpr size_t OFF_M    = 64668352;               // 512*128
constexpr size_t OFF_CP   = 64733888;               // 128
constexpr size_t BUF_TOTAL = 64734016;

__device__ __align__(16) float g_buf[BUF_TOTAL];

__device__ __forceinline__ float wsum(float v) {
#pragma unroll
    for (int o = 16; o > 0; o >>= 1) v += __shfl_xor_sync(0xffffffffu, v, o);
    return v;
}
__device__ __forceinline__ float wmax(float v) {
#pragma unroll
    for (int o = 16; o > 0; o >>= 1) v = fmaxf(v, __shfl_xor_sync(0xffffffffu, v, o));
    return v;
}

// ---------------------------------------------------------------------------
// prep_small: qvec, wscore, cscore, cpool   (1 block, 128 threads)
// ---------------------------------------------------------------------------
__global__ void prep_small(const float* __restrict__ cls,
                           const float* __restrict__ ipW,  // (384,128)
                           const float* __restrict__ ipB,  // (384,)
                           const float* __restrict__ opW,  // (128,128)
                           const float* __restrict__ opB)  // (128,)
{
    int tid = threadIdx.x;  // 0..127
    float* qvec   = g_buf + OFF_QVEC;
    float* wscore = g_buf + OFF_WS;
    float* cscore = g_buf + OFF_CS;
    float* cpool  = g_buf + OFF_CP;

    // q = cls @ W_q^T + b_q
    {
        float q = ipB[tid];
        const float* wrow = ipW + (size_t)tid * 128;
        for (int d = 0; d < 128; d++) q += cls[d] * wrow[d];
        qvec[tid] = q;
    }
    __syncthreads();

    const float rs = 0.17677669529663687f;  // 1/sqrt(32)
    // wscore[h*128+d] = sum_e q[32h+e] * W_k[32h+e, d] * rs
    for (int idx = tid; idx < 512; idx += 128) {
        int h = idx >> 7, d = idx & 127;
        float s = 0.f;
        for (int e = 0; e < 32; e++)
            s += qvec[h * 32 + e] * ipW[(size_t)(128 + h * 32 + e) * 128 + d];
        wscore[idx] = s * rs;
    }
    if (tid < 4) {
        float s = 0.f;
        for (int e = 0; e < 32; e++)
            s += qvec[tid * 32 + e] * ipB[128 + tid * 32 + e];
        cscore[tid] = s * rs;
    }
    // cpool[d] = sum_e W_o[d,e]*b_v[e] + b_o[d]
    {
        float c = opB[tid];
        const float* orow = opW + (size_t)tid * 128;
        for (int e = 0; e < 128; e++) c += orow[e] * ipB[256 + e];
        cpool[tid] = c;
    }
}

// ---------------------------------------------------------------------------
// prep_M: Mflat[(h*128+c)*128 + d] = sum_e W_v[32h+e, c] * W_o[d, 32h+e]
// ---------------------------------------------------------------------------
__global__ void prep_M(const float* __restrict__ ipW, const float* __restrict__ opW)
{
    int idx = blockIdx.x * blockDim.x + threadIdx.x;  // < 65536
    if (idx >= 512 * 128) return;
    int d = idx & 127;
    int k = idx >> 7;       // 0..511
    int h = k >> 7;         // 0..3
    int c = k & 127;
    float s = 0.f;
    for (int e = 0; e < 32; e++)
        s += ipW[(size_t)(256 + h * 32 + e) * 128 + c] * opW[(size_t)d * 128 + h * 32 + e];
    g_buf[OFF_M + (size_t)k * 128 + d] = s;
}

// ---------------------------------------------------------------------------
// attention kernel: one block per batch item, 128 threads (4 warps)
// outputs XW (B x 512): head-weighted sums of token embeddings
// ---------------------------------------------------------------------------
__device__ __forceinline__ void slot_info(int s, int& cat, int& off) {
    const int defs[9] = {16, 8, 4, 4, 4, 8, 8, 8, 8};
    int base = 59, acc = 0;
#pragma unroll
    for (int c = 0; c < 9; c++) {
        if (s < acc + defs[c]) { cat = c; off = base + 1 + (s - acc) * 4; return; }
        acc += defs[c];
        base += 1 + defs[c] * 4;
    }
    cat = 8; off = 0;
}

__global__ __launch_bounds__(128)
void attn_k(const float* __restrict__ state,
            const float* __restrict__ embW, const float* __restrict__ embB,
            const float* __restrict__ lng,  const float* __restrict__ lnb,
            const float* __restrict__ cls)
{
    int b = blockIdx.x;
    int tid = threadIdx.x;
    int lane = tid & 31, warp = tid >> 5;

    __shared__ float xs[69][128];
    __shared__ float tokf[68][8];
    __shared__ float sc[4][72];
    __shared__ int s_any;

    const float* st = state + (size_t)b * STATE_SZ;
    float presv = 0.f;
    if (tid < 68) {
        int cat, off;
        slot_info(tid, cat, off);
        float p   = st[1020 + off + 0];
        float dx  = st[1020 + off + 1];
        float dy  = st[1020 + off + 2];
        float di  = st[1020 + off + 3];
        float pp  = st[680 + off + 0];
        float pdx = st[680 + off + 1];
        float pdy = st[680 + off + 2];
        float vv  = (p > 0.5f && pp > 0.5f) ? 1.f : 0.f;
        tokf[tid][0] = dx;
        tokf[tid][1] = dy;
        tokf[tid][2] = di;
        tokf[tid][3] = (dx - pdx) * vv;
        tokf[tid][4] = (dy - pdy) * vv;
        tokf[tid][5] = (float)cat * 0.125f;
        tokf[tid][6] = p;
        presv = p;
    }
    if (tid == 127) s_any = 0;
    __syncthreads();
    if (tid < 68 && presv >= 0.5f) atomicOr(&s_any, 1);
    __syncthreads();
    int all_empty = (s_any == 0);

    const float* wsc = g_buf + OFF_WS;
    const float* csc = g_buf + OFF_CS;

    // warp-per-token: embed + layernorm + scores
    for (int j = warp; j < 69; j += 4) {
        float xv[4];
        if (j == 0) {
#pragma unroll
            for (int q = 0; q < 4; q++) xv[q] = cls[lane + 32 * q];
        } else {
            const float* tf = tokf[j - 1];
            float f0 = tf[0], f1 = tf[1], f2 = tf[2], f3 = tf[3], f4 = tf[4], f5 = tf[5], f6 = tf[6];
#pragma unroll
            for (int q = 0; q < 4; q++) {
                int d = lane + 32 * q;
                float e = embB[d];
                e += f0 * embW[0 * 128 + d];
                e += f1 * embW[1 * 128 + d];
                e += f2 * embW[2 * 128 + d];
                e += f3 * embW[3 * 128 + d];
                e += f4 * embW[4 * 128 + d];
                e += f5 * embW[5 * 128 + d];
                e += f6 * embW[6 * 128 + d];
                xv[q] = e;
            }
            float s = xv[0] + xv[1] + xv[2] + xv[3];
            float ss = xv[0]*xv[0] + xv[1]*xv[1] + xv[2]*xv[2] + xv[3]*xv[3];
            s = wsum(s); ss = wsum(ss);
            float mean = s * (1.f / 128.f);
            float var  = ss * (1.f / 128.f) - mean * mean;
            float inv  = rsqrtf(var + 1e-5f);
#pragma unroll
            for (int q = 0; q < 4; q++) {
                int d = lane + 32 * q;
                xv[q] = (xv[q] - mean) * inv * lng[d] + lnb[d];
            }
        }
#pragma unroll
        for (int q = 0; q < 4; q++) xs[j][lane + 32 * q] = xv[q];

        float s0 = 0, s1 = 0, s2 = 0, s3 = 0;
#pragma unroll
        for (int q = 0; q < 4; q++) {
            int d = lane + 32 * q;
            float x = xv[q];
            s0 += x * wsc[d];
            s1 += x * wsc[128 + d];
            s2 += x * wsc[256 + d];
            s3 += x * wsc[384 + d];
        }
        s0 = wsum(s0); s1 = wsum(s1); s2 = wsum(s2); s3 = wsum(s3);
        if (lane == 0) {
            bool masked = (j > 0) && (tokf[j - 1][6] < 0.5f) && !all_empty;
            sc[0][j] = masked ? -1e9f : s0 + csc[0];
            sc[1][j] = masked ? -1e9f : s1 + csc[1];
            sc[2][j] = masked ? -1e9f : s2 + csc[2];
            sc[3][j] = masked ? -1e9f : s3 + csc[3];
        }
    }
    __syncthreads();

    // softmax per head (warp h)
    {
        int h = warp;
        float v0 = (lane < 69)      ? sc[h][lane]      : -1e30f;
        float v1 = (lane + 32 < 69) ? sc[h][lane + 32] : -1e30f;
        float v2 = (lane + 64 < 69) ? sc[h][lane + 64] : -1e30f;
        float m = wmax(fmaxf(fmaxf(v0, v1), v2));
        float e0 = (lane < 69)      ? expf(v0 - m) : 0.f;
        float e1 = (lane + 32 < 69) ? expf(v1 - m) : 0.f;
        float e2 = (lane + 64 < 69) ? expf(v2 - m) : 0.f;
        float s = wsum(e0 + e1 + e2);
        float inv = 1.f / s;
        if (lane < 69)      sc[h][lane]      = e0 * inv;
        if (lane + 32 < 69) sc[h][lane + 32] = e1 * inv;
        if (lane + 64 < 69) sc[h][lane + 64] = e2 * inv;
    }
    __syncthreads();

    // xw_h[d] = sum_j a_hj * x_j[d]
    {
        int d = tid;
        float a0 = 0, a1 = 0, a2 = 0, a3 = 0;
        for (int j = 0; j < 69; j++) {
            float x = xs[j][d];
            a0 += sc[0][j] * x;
            a1 += sc[1][j] * x;
            a2 += sc[2][j] * x;
            a3 += sc[3][j] * x;
        }
        float* xw = g_buf + OFF_XW + (size_t)b * 512;
        xw[d]       = a0;
        xw[128 + d] = a1;
        xw[256 + d] = a2;
        xw[384 + d] = a3;
    }
}

// ---------------------------------------------------------------------------
// generic SGEMM: C(MxN) = A(MxK) @ B(KxN) + bias, optional relu, optional
// concatenated A (k < splitK from A, else A2). BM=BN=128, BK=8, 8x8/thread.
// ---------------------------------------------------------------------------
template <bool SPLITA, bool VECB, int ACT>
__global__ __launch_bounds__(256, 2)
void gemm_k(int M, int N, int K,
            const float* __restrict__ A, int lda, int splitK,
            const float* __restrict__ A2, int lda2,
            const float* __restrict__ B,
            const float* __restrict__ bias,
            float* __restrict__ C)
{
    __shared__ float As[8][128];
    __shared__ float Bs[8][128];
    int tid = threadIdx.x;
    int bm = blockIdx.y * 128;
    int bn = blockIdx.x * 128;
    int tr = tid / 16;
    int tc = tid % 16;
    int aRow = tid >> 1;
    int aCol = (tid & 1) * 4;
    int bRow = tid >> 5;
    int bCol = (tid & 31) * 4;

    float acc[8][8];
#pragma unroll
    for (int i = 0; i < 8; i++)
#pragma unroll
        for (int j = 0; j < 8; j++) acc[i][j] = 0.f;

    for (int k0 = 0; k0 < K; k0 += 8) {
        // A tile (always valid rows; K multiple of 8; split boundary 8-aligned)
        {
            int gRow = bm + aRow;
            int gk = k0 + aCol;
            float4 av;
            if (!SPLITA || gk < splitK) {
                av = *reinterpret_cast<const float4*>(&A[(size_t)gRow * lda + gk]);
            } else {
                av = *reinterpret_cast<const float4*>(&A2[(size_t)gRow * lda2 + (gk - splitK)]);
            }
            As[aCol + 0][aRow] = av.x;
            As[aCol + 1][aRow] = av.y;
            As[aCol + 2][aRow] = av.z;
            As[aCol + 3][aRow] = av.w;
        }
        // B tile
        {
            int gk = k0 + bRow;
            if (VECB) {
                float4 bv = *reinterpret_cast<const float4*>(&B[(size_t)gk * N + bn + bCol]);
                Bs[bRow][bCol + 0] = bv.x;
                Bs[bRow][bCol + 1] = bv.y;
                Bs[bRow][bCol + 2] = bv.z;
                Bs[bRow][bCol + 3] = bv.w;
            } else {
#pragma unroll
                for (int i = 0; i < 4; i++) {
                    int col = bn + bCol + i;
                    Bs[bRow][bCol + i] = (col < N) ? B[(size_t)gk * N + col] : 0.f;
                }
            }
        }
        __syncthreads();
#pragma unroll
        for (int kk = 0; kk < 8; kk++) {
            float rm[8], rn[8];
#pragma unroll
            for (int i = 0; i < 8; i++) rm[i] = As[kk][tr * 8 + i];
#pragma unroll
            for (int j = 0; j < 8; j++) rn[j] = Bs[kk][tc * 8 + j];
#pragma unroll
            for (int i = 0; i < 8; i++)
#pragma unroll
                for (int j = 0; j < 8; j++) acc[i][j] += rm[i] * rn[j];
        }
        __syncthreads();
    }
#pragma unroll
    for (int i = 0; i < 8; i++) {
        int row = bm + tr * 8 + i;
#pragma unroll
        for (int j = 0; j < 8; j++) {
            int col = bn + tc * 8 + j;
            if (col < N) {
                float v = acc[i][j] + bias[col];
                if (ACT == 1) v = fmaxf(v, 0.f);
                C[(size_t)row * N + col] = v;
            }
        }
    }
}

// ---------------------------------------------------------------------------
// rowwise layernorm + relu (in-place), one block per row
// ---------------------------------------------------------------------------
__global__ void ln_relu_k(float* __restrict__ x, const float* __restrict__ g,
                          const float* __restrict__ bta, int L)
{
    size_t row = blockIdx.x;
    float* p = x + row * (size_t)L;
    int tid = threadIdx.x;
    float s = 0.f, ss = 0.f;
    for (int i = tid; i < L; i += 256) {
        float v = p[i];
        s += v; ss += v * v;
    }
    __shared__ float sh1[8], sh2[8];
    s = wsum(s); ss = wsum(ss);
    int w = tid >> 5, l = tid & 31;
    if (l == 0) { sh1[w] = s; sh2[w] = ss; }
    __syncthreads();
    if (w == 0) {
        float a = (l < 8) ? sh1[l] : 0.f;
        float c = (l < 8) ? sh2[l] : 0.f;
        a = wsum(a); c = wsum(c);
        if (l == 0) { sh1[0] = a; sh2[0] = c; }
    }
    __syncthreads();
    float mean = sh1[0] / (float)L;
    float var  = sh2[0] / (float)L - mean * mean;
    float inv  = rsqrtf(var + 1e-5f);
    for (int i = tid; i < L; i += 256) {
        float v = p[i];
        p[i] = fmaxf((v - mean) * inv * g[i] + bta[i], 0.f);
    }
}

// ---------------------------------------------------------------------------
// final dueling head + softmax over atoms; one block per batch item
// ---------------------------------------------------------------------------
__global__ __launch_bounds__(256)
void final_k(float* __restrict__ out)
{
    int b = blockIdx.x;
    int tid = threadIdx.x;
    __shared__ float sadv[ADV_N];
    __shared__ float cm[ATOMS];
    __shared__ float sval[ATOMS];
    const float* ap = g_buf + OFF_ADV + (size_t)b * ADV_N;
    const float* vp = g_buf + OFF_VAL + (size_t)b * ATOMS;
    for (int i = tid; i < ADV_N; i += 256) sadv[i] = ap[i];
    if (tid < ATOMS) sval[tid] = vp[tid];
    __syncthreads();
    if (tid < ATOMS) {
        float s = 0.f;
#pragma unroll
        for (int a = 0; a < ACTIONS; a++) s += sadv[a * ATOMS + tid];
        cm[tid] = s * (1.f / 81.f);
    }
    __syncthreads();
    int w = tid >> 5, l = tid & 31;
    float* op = out + (size_t)b * ADV_N;
    for (int a = w; a < ACTIONS; a += 8) {
        float q0 = (l < ATOMS)      ? sval[l]      + sadv[a * ATOMS + l]      - cm[l]      : -1e30f;
        float q1 = (l + 32 < ATOMS) ? sval[l + 32] + sadv[a * ATOMS + l + 32] - cm[l + 32] : -1e30f;
        float m = wmax(fmaxf(q0, q1));
        float e0 = (l < ATOMS)      ? expf(q0 - m) : 0.f;
        float e1 = (l + 32 < ATOMS) ? expf(q1 - m) : 0.f;
        float s = wsum(e0 + e1);
        float inv = 1.f / s;
        if (l < ATOMS)      op[a * ATOMS + l]      = e0 * inv;
        if (l + 32 < ATOMS) op[a * ATOMS + l + 32] = e1 * inv;
    }
}

// ---------------------------------------------------------------------------
extern "C" void kernel_launch(void* const* d_in, const int* in_sizes, int n_in,
                              void* d_out, int out_size)
{
    const float* state     = (const float*)d_in[0];
    const float* embed_W   = (const float*)d_in[1];
    const float* embed_b   = (const float*)d_in[2];
    const float* ln_g      = (const float*)d_in[3];
    const float* ln_b      = (const float*)d_in[4];
    const float* cls_tok   = (const float*)d_in[5];
    const float* in_proj_W = (const float*)d_in[6];
    const float* in_proj_b = (const float*)d_in[7];
    const float* out_proj_W= (const float*)d_in[8];
    const float* out_proj_b= (const float*)d_in[9];
    const float* t0_W      = (const float*)d_in[10];
    const float* t0_b      = (const float*)d_in[11];
    const float* t0_g      = (const float*)d_in[12];
    const float* t0_beta   = (const float*)d_in[13];
    const float* t1_W      = (const float*)d_in[14];
    const float* t1_b      = (const float*)d_in[15];
    const float* t1_g      = (const float*)d_in[16];
    const float* t1_beta   = (const float*)d_in[17];
    const float* val_fc_W  = (const float*)d_in[18];
    const float* val_fc_b  = (const float*)d_in[19];
    const float* val_out_W = (const float*)d_in[20];
    const float* val_out_b = (const float*)d_in[21];
    const float* adv_fc_W  = (const float*)d_in[22];
    const float* adv_fc_b  = (const float*)d_in[23];
    const float* adv_out_W = (const float*)d_in[24];
    const float* adv_out_b = (const float*)d_in[25];
    float* out = (float*)d_out;

    float* buf = nullptr;
    cudaGetSymbolAddress((void**)&buf, g_buf);
    float* xw     = buf + OFF_XW;
    float* pooled = buf + OFF_POOL;
    float* z0     = buf + OFF_Z0;
    float* h1     = buf + OFF_H1;
    float* valh   = buf + OFF_VALH;
    float* advh   = buf + OFF_ADVH;
    float* val    = buf + OFF_VAL;
    float* adv    = buf + OFF_ADV;
    float* Mflat  = buf + OFF_M;
    float* cpool  = buf + OFF_CP;

    // precompute folded attention constants
    prep_small<<<1, 128>>>(cls_tok, in_proj_W, in_proj_b, out_proj_W, out_proj_b);
    prep_M<<<256, 256>>>(in_proj_W, out_proj_W);

    // per-batch token build + embed + LN + scores + softmax + weighted sums
    attn_k<<<BQ, 128>>>(state, embed_W, embed_b, ln_g, ln_b, cls_tok);

    // pooled = XW @ Mflat + cpool
    gemm_k<false, true, 0><<<dim3(1, 64), 256>>>(BQ, 128, 512, xw, 512, 0, xw, 0,
                                                 Mflat, cpool, pooled);
    // trunk 0: [state | pooled] @ t0_W + t0_b
    gemm_k<true, true, 0><<<dim3(8, 64), 256>>>(BQ, TRUNK_H, TRUNK_IN,
                                                state, STATE_SZ, STATE_SZ,
                                                pooled, 128, t0_W, t0_b, z0);
    ln_relu_k<<<BQ, 256>>>(z0, t0_g, t0_beta, TRUNK_H);

    // trunk 1
    gemm_k<false, true, 0><<<dim3(8, 64), 256>>>(BQ, TRUNK_H, TRUNK_H,
                                                 z0, TRUNK_H, 0, z0, 0, t1_W, t1_b, h1);
    ln_relu_k<<<BQ, 256>>>(h1, t1_g, t1_beta, TRUNK_H);

    // heads (relu fused in epilogue)
    gemm_k<false, true, 1><<<dim3(4, 64), 256>>>(BQ, HALF_H, TRUNK_H,
                                                 h1, TRUNK_H, 0, h1, 0, val_fc_W, val_fc_b, valh);
    gemm_k<false, true, 1><<<dim3(4, 64), 256>>>(BQ, HALF_H, TRUNK_H,
                                                 h1, TRUNK_H, 0, h1, 0, adv_fc_W, adv_fc_b, advh);
    gemm_k<false, false, 0><<<dim3(1, 64), 256>>>(BQ, ATOMS, HALF_H,
                                                  valh, HALF_H, 0, valh, 0, val_out_W, val_out_b, val);
    gemm_k<false, false, 0><<<dim3(33, 64), 256>>>(BQ, ADV_N, HALF_H,
                                                   advh, HALF_H, 0, advh, 0, adv_out_W, adv_out_b, adv);

    // dueling + atom softmax
    final_k<<<BQ, 256>>>(out);
    (void)in_sizes; (void)n_in; (void)out_size;
}

// round 3
// speedup vs baseline: 2.3019x; 2.3019x over previous
#include <cuda_runtime.h>
#include <math.h>
#include <stdint.h>

// ---------------------------------------------------------------------------
// RainbowNet fused inference — tf32 tensor-core GEMM edition.
// Attention is algebraically folded (cls-query is batch-independent):
//   scores[h,j] = x_j . wscore_h + c_h
//   pooled      = XW @ Mflat + c_pool
// All trunk GEMMs run on mma.sync.m16n8k8 tf32 with fp32 accumulation.
// ---------------------------------------------------------------------------

constexpr int BQ       = 8192;
constexpr int STATE_SZ = 1360;
constexpr int TRUNK_IN = 1488;   // 1360 + 128
constexpr int TRUNK_H  = 1024;
constexpr int HALF_H   = 512;
constexpr int ATOMS    = 51;
constexpr int ACTIONS  = 81;
constexpr int ADV_N    = ACTIONS * ATOMS;  // 4131

// scratch offsets (floats)
constexpr size_t OFF_XW   = 0;                      // 8192*512
constexpr size_t OFF_POOL = 4194304;                // 8192*128
constexpr size_t OFF_Z0   = 5242880;                // 8192*1024
constexpr size_t OFF_H1   = 13631488;               // 8192*1024
constexpr size_t OFF_VALH = 22020096;               // 8192*512
constexpr size_t OFF_ADVH = 26214400;               // 8192*512
constexpr size_t OFF_VAL  = 30408704;               // 8192*51
constexpr size_t OFF_ADV  = 30826496;               // 8192*4131
constexpr size_t OFF_QVEC = 64667648;               // 128
constexpr size_t OFF_WS   = 64667776;               // 512
constexpr size_t OFF_CS   = 64668288;               // 64 (4 used)
constexpr size_t OFF_M    = 64668352;               // 512*128
constexpr size_t OFF_CP   = 64733888;               // 128
constexpr size_t BUF_TOTAL = 64734016;

__device__ __align__(16) float g_buf[BUF_TOTAL];

__device__ __forceinline__ float wsum(float v) {
#pragma unroll
    for (int o = 16; o > 0; o >>= 1) v += __shfl_xor_sync(0xffffffffu, v, o);
    return v;
}
__device__ __forceinline__ float wmax(float v) {
#pragma unroll
    for (int o = 16; o > 0; o >>= 1) v = fmaxf(v, __shfl_xor_sync(0xffffffffu, v, o));
    return v;
}

__device__ __forceinline__ float to_tf32(float x) {
    uint32_t u;
    asm("cvt.rna.tf32.f32 %0, %1;" : "=r"(u) : "f"(x));
    return __uint_as_float(u);
}

// ---------------------------------------------------------------------------
// prep_small: qvec, wscore, cscore, cpool   (1 block, 128 threads)
// ---------------------------------------------------------------------------
__global__ void prep_small(const float* __restrict__ cls,
                           const float* __restrict__ ipW,  // (384,128)
                           const float* __restrict__ ipB,  // (384,)
                           const float* __restrict__ opW,  // (128,128)
                           const float* __restrict__ opB)  // (128,)
{
    int tid = threadIdx.x;  // 0..127
    float* qvec   = g_buf + OFF_QVEC;
    float* wscore = g_buf + OFF_WS;
    float* cscore = g_buf + OFF_CS;
    float* cpool  = g_buf + OFF_CP;

    {
        float q = ipB[tid];
        const float* wrow = ipW + (size_t)tid * 128;
        for (int d = 0; d < 128; d++) q += cls[d] * wrow[d];
        qvec[tid] = q;
    }
    __syncthreads();

    const float rs = 0.17677669529663687f;  // 1/sqrt(32)
    for (int idx = tid; idx < 512; idx += 128) {
        int h = idx >> 7, d = idx & 127;
        float s = 0.f;
        for (int e = 0; e < 32; e++)
            s += qvec[h * 32 + e] * ipW[(size_t)(128 + h * 32 + e) * 128 + d];
        wscore[idx] = s * rs;
    }
    if (tid < 4) {
        float s = 0.f;
        for (int e = 0; e < 32; e++)
            s += qvec[tid * 32 + e] * ipB[128 + tid * 32 + e];
        cscore[tid] = s * rs;
    }
    {
        float c = opB[tid];
        const float* orow = opW + (size_t)tid * 128;
        for (int e = 0; e < 128; e++) c += orow[e] * ipB[256 + e];
        cpool[tid] = c;
    }
}

// ---------------------------------------------------------------------------
// prep_M: Mflat[(h*128+c)*128 + d] = sum_e W_v[32h+e, c] * W_o[d, 32h+e]
// ---------------------------------------------------------------------------
__global__ void prep_M(const float* __restrict__ ipW, const float* __restrict__ opW)
{
    int idx = blockIdx.x * blockDim.x + threadIdx.x;
    if (idx >= 512 * 128) return;
    int d = idx & 127;
    int k = idx >> 7;
    int h = k >> 7;
    int c = k & 127;
    float s = 0.f;
    for (int e = 0; e < 32; e++)
        s += ipW[(size_t)(256 + h * 32 + e) * 128 + c] * opW[(size_t)d * 128 + h * 32 + e];
    g_buf[OFF_M + (size_t)k * 128 + d] = s;
}

// ---------------------------------------------------------------------------
// attention kernel: one block per batch item, 128 threads (4 warps)
// ---------------------------------------------------------------------------
__device__ __forceinline__ void slot_info(int s, int& cat, int& off) {
    const int defs[9] = {16, 8, 4, 4, 4, 8, 8, 8, 8};
    int base = 59, acc = 0;
#pragma unroll
    for (int c = 0; c < 9; c++) {
        if (s < acc + defs[c]) { cat = c; off = base + 1 + (s - acc) * 4; return; }
        acc += defs[c];
        base += 1 + defs[c] * 4;
    }
    cat = 8; off = 0;
}

__global__ __launch_bounds__(128)
void attn_k(const float* __restrict__ state,
            const float* __restrict__ embW, const float* __restrict__ embB,
            const float* __restrict__ lng,  const float* __restrict__ lnb,
            const float* __restrict__ cls)
{
    int b = blockIdx.x;
    int tid = threadIdx.x;
    int lane = tid & 31, warp = tid >> 5;

    __shared__ float xs[69][128];
    __shared__ float tokf[68][8];
    __shared__ float sc[4][72];
    __shared__ int s_any;

    const float* st = state + (size_t)b * STATE_SZ;
    float presv = 0.f;
    if (tid < 68) {
        int cat, off;
        slot_info(tid, cat, off);
        float p   = st[1020 + off + 0];
        float dx  = st[1020 + off + 1];
        float dy  = st[1020 + off + 2];
        float di  = st[1020 + off + 3];
        float pp  = st[680 + off + 0];
        float pdx = st[680 + off + 1];
        float pdy = st[680 + off + 2];
        float vv  = (p > 0.5f && pp > 0.5f) ? 1.f : 0.f;
        tokf[tid][0] = dx;
        tokf[tid][1] = dy;
        tokf[tid][2] = di;
        tokf[tid][3] = (dx - pdx) * vv;
        tokf[tid][4] = (dy - pdy) * vv;
        tokf[tid][5] = (float)cat * 0.125f;
        tokf[tid][6] = p;
        presv = p;
    }
    if (tid == 127) s_any = 0;
    __syncthreads();
    if (tid < 68 && presv >= 0.5f) atomicOr(&s_any, 1);
    __syncthreads();
    int all_empty = (s_any == 0);

    const float* wsc = g_buf + OFF_WS;
    const float* csc = g_buf + OFF_CS;

    for (int j = warp; j < 69; j += 4) {
        float xv[4];
        if (j == 0) {
#pragma unroll
            for (int q = 0; q < 4; q++) xv[q] = cls[lane + 32 * q];
        } else {
            const float* tf = tokf[j - 1];
            float f0 = tf[0], f1 = tf[1], f2 = tf[2], f3 = tf[3], f4 = tf[4], f5 = tf[5], f6 = tf[6];
#pragma unroll
            for (int q = 0; q < 4; q++) {
                int d = lane + 32 * q;
                float e = embB[d];
                e += f0 * embW[0 * 128 + d];
                e += f1 * embW[1 * 128 + d];
                e += f2 * embW[2 * 128 + d];
                e += f3 * embW[3 * 128 + d];
                e += f4 * embW[4 * 128 + d];
                e += f5 * embW[5 * 128 + d];
                e += f6 * embW[6 * 128 + d];
                xv[q] = e;
            }
            float s = xv[0] + xv[1] + xv[2] + xv[3];
            float ss = xv[0]*xv[0] + xv[1]*xv[1] + xv[2]*xv[2] + xv[3]*xv[3];
            s = wsum(s); ss = wsum(ss);
            float mean = s * (1.f / 128.f);
            float var  = ss * (1.f / 128.f) - mean * mean;
            float inv  = rsqrtf(var + 1e-5f);
#pragma unroll
            for (int q = 0; q < 4; q++) {
                int d = lane + 32 * q;
                xv[q] = (xv[q] - mean) * inv * lng[d] + lnb[d];
            }
        }
#pragma unroll
        for (int q = 0; q < 4; q++) xs[j][lane + 32 * q] = xv[q];

        float s0 = 0, s1 = 0, s2 = 0, s3 = 0;
#pragma unroll
        for (int q = 0; q < 4; q++) {
            int d = lane + 32 * q;
            float x = xv[q];
            s0 += x * wsc[d];
            s1 += x * wsc[128 + d];
            s2 += x * wsc[256 + d];
            s3 += x * wsc[384 + d];
        }
        s0 = wsum(s0); s1 = wsum(s1); s2 = wsum(s2); s3 = wsum(s3);
        if (lane == 0) {
            bool masked = (j > 0) && (tokf[j - 1][6] < 0.5f) && !all_empty;
            sc[0][j] = masked ? -1e9f : s0 + csc[0];
            sc[1][j] = masked ? -1e9f : s1 + csc[1];
            sc[2][j] = masked ? -1e9f : s2 + csc[2];
            sc[3][j] = masked ? -1e9f : s3 + csc[3];
        }
    }
    __syncthreads();

    {
        int h = warp;
        float v0 = (lane < 69)      ? sc[h][lane]      : -1e30f;
        float v1 = (lane + 32 < 69) ? sc[h][lane + 32] : -1e30f;
        float v2 = (lane + 64 < 69) ? sc[h][lane + 64] : -1e30f;
        float m = wmax(fmaxf(fmaxf(v0, v1), v2));
        float e0 = (lane < 69)      ? expf(v0 - m) : 0.f;
        float e1 = (lane + 32 < 69) ? expf(v1 - m) : 0.f;
        float e2 = (lane + 64 < 69) ? expf(v2 - m) : 0.f;
        float s = wsum(e0 + e1 + e2);
        float inv = 1.f / s;
        if (lane < 69)      sc[h][lane]      = e0 * inv;
        if (lane + 32 < 69) sc[h][lane + 32] = e1 * inv;
        if (lane + 64 < 69) sc[h][lane + 64] = e2 * inv;
    }
    __syncthreads();

    {
        int d = tid;
        float a0 = 0, a1 = 0, a2 = 0, a3 = 0;
        for (int j = 0; j < 69; j++) {
            float x = xs[j][d];
            a0 += sc[0][j] * x;
            a1 += sc[1][j] * x;
            a2 += sc[2][j] * x;
            a3 += sc[3][j] * x;
        }
        float* xw = g_buf + OFF_XW + (size_t)b * 512;
        xw[d]       = a0;
        xw[128 + d] = a1;
        xw[256 + d] = a2;
        xw[384 + d] = a3;
    }
}

// ---------------------------------------------------------------------------
// tf32 tensor-core GEMM: C(MxN) = A(MxK) @ B(KxN) + bias [+relu]
// BM=BN=128, BK=16, 256 threads (8 warps, 2x4 grid of 64x32 warp tiles).
// Double-buffered smem, register-staged global loads, cvt.rna.tf32 on fill.
// SPLITA: k < splitK reads A (lda), else A2 (lda2).  Boundary 16-aligned.
// VECB: B rows are float4-aligned (N % 4 == 0).
// ---------------------------------------------------------------------------
template <bool SPLITA, bool VECB, int ACT>
__global__ __launch_bounds__(256, 2)
void gemm_tf32(int M, int N, int K,
               const float* __restrict__ A, int lda, int splitK,
               const float* __restrict__ A2, int lda2,
               const float* __restrict__ B,
               const float* __restrict__ bias,
               float* __restrict__ C)
{
    constexpr int BM = 128, BN = 128, BK = 16;
    constexpr int APAD = 4;   // As row stride 20
    constexpr int BPAD = 8;   // Bs row stride 136
    __shared__ __align__(16) float As[2][BM][BK + APAD];
    __shared__ __align__(16) float Bs[2][BK][BN + BPAD];

    int tid  = threadIdx.x;
    int lane = tid & 31;
    int warp = tid >> 5;
    int wm = (warp >> 2) * 64;  // 0 or 64
    int wn = (warp & 3) * 32;   // 0,32,64,96
    int bm = blockIdx.y * BM;
    int bn = blockIdx.x * BN;

    // fill maps (2 float4 per thread for each of A,B)
    int aRow = tid >> 2;            // + 64*i
    int aK   = (tid & 3) * 4;
    int bRow = tid >> 5;            // + 8*i
    int bCol = (tid & 31) * 4;

    float acc[4][4][4];
#pragma unroll
    for (int i = 0; i < 4; i++)
#pragma unroll
        for (int j = 0; j < 4; j++)
#pragma unroll
            for (int c = 0; c < 4; c++) acc[i][j][c] = 0.f;

    float4 avS[2], bvS[2];

    auto loadTiles = [&](int k0) {
#pragma unroll
        for (int i = 0; i < 2; i++) {
            int r  = bm + aRow + 64 * i;
            int gk = k0 + aK;
            const float* src;
            if (!SPLITA || gk < splitK)
                src = &A[(size_t)r * lda + gk];
            else
                src = &A2[(size_t)r * lda2 + (gk - splitK)];
            avS[i] = *reinterpret_cast<const float4*>(src);
        }
#pragma unroll
        for (int i = 0; i < 2; i++) {
            int kr = k0 + bRow + 8 * i;
            int nc = bn + bCol;
            if (VECB) {
                bvS[i] = *reinterpret_cast<const float4*>(&B[(size_t)kr * N + nc]);
            } else {
                float t0 = (nc + 0 < N) ? B[(size_t)kr * N + nc + 0] : 0.f;
                float t1 = (nc + 1 < N) ? B[(size_t)kr * N + nc + 1] : 0.f;
                float t2 = (nc + 2 < N) ? B[(size_t)kr * N + nc + 2] : 0.f;
                float t3 = (nc + 3 < N) ? B[(size_t)kr * N + nc + 3] : 0.f;
                bvS[i] = make_float4(t0, t1, t2, t3);
            }
        }
    };

    auto storeStage = [&](int s) {
#pragma unroll
        for (int i = 0; i < 2; i++) {
            float4 v = avS[i];
            v.x = to_tf32(v.x); v.y = to_tf32(v.y);
            v.z = to_tf32(v.z); v.w = to_tf32(v.w);
            *reinterpret_cast<float4*>(&As[s][aRow + 64 * i][aK]) = v;
        }
#pragma unroll
        for (int i = 0; i < 2; i++) {
            float4 v = bvS[i];
            v.x = to_tf32(v.x); v.y = to_tf32(v.y);
            v.z = to_tf32(v.z); v.w = to_tf32(v.w);
            *reinterpret_cast<float4*>(&Bs[s][bRow + 8 * i][bCol]) = v;
        }
    };

    int ntiles = K / BK;
    loadTiles(0);
    int s = 0;

    for (int t = 0; t < ntiles; t++) {
        storeStage(s);
        __syncthreads();
        if (t + 1 < ntiles) loadTiles((t + 1) * BK);

#pragma unroll
        for (int kk = 0; kk < 2; kk++) {
            int kc = kk * 8;
            int kf = kc + (lane & 3);
            int rf = wm + (lane >> 2);
            int nf = wn + (lane >> 2);
            uint32_t af[4][4];
#pragma unroll
            for (int i = 0; i < 4; i++) {
                af[i][0] = __float_as_uint(As[s][rf + 16 * i][kf]);
                af[i][1] = __float_as_uint(As[s][rf + 16 * i + 8][kf]);
                af[i][2] = __float_as_uint(As[s][rf + 16 * i][kf + 4]);
                af[i][3] = __float_as_uint(As[s][rf + 16 * i + 8][kf + 4]);
            }
            uint32_t bf[4][2];
#pragma unroll
            for (int j = 0; j < 4; j++) {
                bf[j][0] = __float_as_uint(Bs[s][kf][nf + 8 * j]);
                bf[j][1] = __float_as_uint(Bs[s][kf + 4][nf + 8 * j]);
            }
#pragma unroll
            for (int i = 0; i < 4; i++) {
#pragma unroll
                for (int j = 0; j < 4; j++) {
                    asm volatile(
                        "mma.sync.aligned.m16n8k8.row.col.f32.tf32.tf32.f32 "
                        "{%0,%1,%2,%3},{%4,%5,%6,%7},{%8,%9},{%0,%1,%2,%3};"
                        : "+f"(acc[i][j][0]), "+f"(acc[i][j][1]),
                          "+f"(acc[i][j][2]), "+f"(acc[i][j][3])
                        : "r"(af[i][0]), "r"(af[i][1]), "r"(af[i][2]), "r"(af[i][3]),
                          "r"(bf[j][0]), "r"(bf[j][1]));
                }
            }
        }
        __syncthreads();
        s ^= 1;
    }

    // epilogue
#pragma unroll
    for (int i = 0; i < 4; i++) {
        int row = bm + wm + 16 * i + (lane >> 2);
#pragma unroll
        for (int j = 0; j < 4; j++) {
            int col = bn + wn + 8 * j + (lane & 3) * 2;
#pragma unroll
            for (int half = 0; half < 2; half++) {
                int r = row + half * 8;
#pragma unroll
                for (int cc = 0; cc < 2; cc++) {
                    int c = col + cc;
                    if (c < N) {
                        float v = acc[i][j][half * 2 + cc] + bias[c];
                        if (ACT == 1) v = fmaxf(v, 0.f);
                        C[(size_t)r * N + c] = v;
                    }
                }
            }
        }
    }
}

// ---------------------------------------------------------------------------
// rowwise layernorm + relu (in-place), one block per row
// ---------------------------------------------------------------------------
__global__ void ln_relu_k(float* __restrict__ x, const float* __restrict__ g,
                          const float* __restrict__ bta, int L)
{
    size_t row = blockIdx.x;
    float* p = x + row * (size_t)L;
    int tid = threadIdx.x;
    float s = 0.f, ss = 0.f;
    for (int i = tid; i < L; i += 256) {
        float v = p[i];
        s += v; ss += v * v;
    }
    __shared__ float sh1[8], sh2[8];
    s = wsum(s); ss = wsum(ss);
    int w = tid >> 5, l = tid & 31;
    if (l == 0) { sh1[w] = s; sh2[w] = ss; }
    __syncthreads();
    if (w == 0) {
        float a = (l < 8) ? sh1[l] : 0.f;
        float c = (l < 8) ? sh2[l] : 0.f;
        a = wsum(a); c = wsum(c);
        if (l == 0) { sh1[0] = a; sh2[0] = c; }
    }
    __syncthreads();
    float mean = sh1[0] / (float)L;
    float var  = sh2[0] / (float)L - mean * mean;
    float inv  = rsqrtf(var + 1e-5f);
    for (int i = tid; i < L; i += 256) {
        float v = p[i];
        p[i] = fmaxf((v - mean) * inv * g[i] + bta[i], 0.f);
    }
}

// ---------------------------------------------------------------------------
// final dueling head + softmax over atoms; one block per batch item
// ---------------------------------------------------------------------------
__global__ __launch_bounds__(256)
void final_k(float* __restrict__ out)
{
    int b = blockIdx.x;
    int tid = threadIdx.x;
    __shared__ float sadv[ADV_N];
    __shared__ float cm[ATOMS];
    __shared__ float sval[ATOMS];
    const float* ap = g_buf + OFF_ADV + (size_t)b * ADV_N;
    const float* vp = g_buf + OFF_VAL + (size_t)b * ATOMS;
    for (int i = tid; i < ADV_N; i += 256) sadv[i] = ap[i];
    if (tid < ATOMS) sval[tid] = vp[tid];
    __syncthreads();
    if (tid < ATOMS) {
        float s = 0.f;
#pragma unroll
        for (int a = 0; a < ACTIONS; a++) s += sadv[a * ATOMS + tid];
        cm[tid] = s * (1.f / 81.f);
    }
    __syncthreads();
    int w = tid >> 5, l = tid & 31;
    float* op = out + (size_t)b * ADV_N;
    for (int a = w; a < ACTIONS; a += 8) {
        float q0 = (l < ATOMS)      ? sval[l]      + sadv[a * ATOMS + l]      - cm[l]      : -1e30f;
        float q1 = (l + 32 < ATOMS) ? sval[l + 32] + sadv[a * ATOMS + l + 32] - cm[l + 32] : -1e30f;
        float m = wmax(fmaxf(q0, q1));
        float e0 = (l < ATOMS)      ? expf(q0 - m) : 0.f;
        float e1 = (l + 32 < ATOMS) ? expf(q1 - m) : 0.f;
        float sm = wsum(e0 + e1);
        float inv = 1.f / sm;
        if (l < ATOMS)      op[a * ATOMS + l]      = e0 * inv;
        if (l + 32 < ATOMS) op[a * ATOMS + l + 32] = e1 * inv;
    }
}

// ---------------------------------------------------------------------------
extern "C" void kernel_launch(void* const* d_in, const int* in_sizes, int n_in,
                              void* d_out, int out_size)
{
    const float* state     = (const float*)d_in[0];
    const float* embed_W   = (const float*)d_in[1];
    const float* embed_b   = (const float*)d_in[2];
    const float* ln_g      = (const float*)d_in[3];
    const float* ln_b      = (const float*)d_in[4];
    const float* cls_tok   = (const float*)d_in[5];
    const float* in_proj_W = (const float*)d_in[6];
    const float* in_proj_b = (const float*)d_in[7];
    const float* out_proj_W= (const float*)d_in[8];
    const float* out_proj_b= (const float*)d_in[9];
    const float* t0_W      = (const float*)d_in[10];
    const float* t0_b      = (const float*)d_in[11];
    const float* t0_g      = (const float*)d_in[12];
    const float* t0_beta   = (const float*)d_in[13];
    const float* t1_W      = (const float*)d_in[14];
    const float* t1_b      = (const float*)d_in[15];
    const float* t1_g      = (const float*)d_in[16];
    const float* t1_beta   = (const float*)d_in[17];
    const float* val_fc_W  = (const float*)d_in[18];
    const float* val_fc_b  = (const float*)d_in[19];
    const float* val_out_W = (const float*)d_in[20];
    const float* val_out_b = (const float*)d_in[21];
    const float* adv_fc_W  = (const float*)d_in[22];
    const float* adv_fc_b  = (const float*)d_in[23];
    const float* adv_out_W = (const float*)d_in[24];
    const float* adv_out_b = (const float*)d_in[25];
    float* out = (float*)d_out;

    float* buf = nullptr;
    cudaGetSymbolAddress((void**)&buf, g_buf);
    float* xw     = buf + OFF_XW;
    float* pooled = buf + OFF_POOL;
    float* z0     = buf + OFF_Z0;
    float* h1     = buf + OFF_H1;
    float* valh   = buf + OFF_VALH;
    float* advh   = buf + OFF_ADVH;
    float* val    = buf + OFF_VAL;
    float* adv    = buf + OFF_ADV;
    float* Mflat  = buf + OFF_M;
    float* cpool  = buf + OFF_CP;

    prep_small<<<1, 128>>>(cls_tok, in_proj_W, in_proj_b, out_proj_W, out_proj_b);
    prep_M<<<256, 256>>>(in_proj_W, out_proj_W);

    attn_k<<<BQ, 128>>>(state, embed_W, embed_b, ln_g, ln_b, cls_tok);

    // pooled = XW @ Mflat + cpool
    gemm_tf32<false, true, 0><<<dim3(1, 64), 256>>>(BQ, 128, 512, xw, 512, 0, xw, 0,
                                                    Mflat, cpool, pooled);
    // trunk 0: [state | pooled] @ t0_W + t0_b
    gemm_tf32<true, true, 0><<<dim3(8, 64), 256>>>(BQ, TRUNK_H, TRUNK_IN,
                                                   state, STATE_SZ, STATE_SZ,
                                                   pooled, 128, t0_W, t0_b, z0);
    ln_relu_k<<<BQ, 256>>>(z0, t0_g, t0_beta, TRUNK_H);

    // trunk 1
    gemm_tf32<false, true, 0><<<dim3(8, 64), 256>>>(BQ, TRUNK_H, TRUNK_H,
                                                    z0, TRUNK_H, 0, z0, 0, t1_W, t1_b, h1);
    ln_relu_k<<<BQ, 256>>>(h1, t1_g, t1_beta, TRUNK_H);

    // heads (relu fused in epilogue)
    gemm_tf32<false, true, 1><<<dim3(4, 64), 256>>>(BQ, HALF_H, TRUNK_H,
                                                    h1, TRUNK_H, 0, h1, 0, val_fc_W, val_fc_b, valh);
    gemm_tf32<false, true, 1><<<dim3(4, 64), 256>>>(BQ, HALF_H, TRUNK_H,
                                                    h1, TRUNK_H, 0, h1, 0, adv_fc_W, adv_fc_b, advh);
    gemm_tf32<false, false, 0><<<dim3(1, 64), 256>>>(BQ, ATOMS, HALF_H,
                                                     valh, HALF_H, 0, valh, 0, val_out_W, val_out_b, val);
    gemm_tf32<false, false, 0><<<dim3(33, 64), 256>>>(BQ, ADV_N, HALF_H,
                                                      advh, HALF_H, 0, advh, 0, adv_out_W, adv_out_b, adv);

    final_k<<<BQ, 256>>>(out);
    (void)in_sizes; (void)n_in; (void)out_size;
}